// round 15
// baseline (speedup 1.0000x reference)
#include <cuda_runtime.h>
#include <math.h>

#define FD 256

// -------- device scratch (zero-initialized at module load) --------
__device__ float g_dist[128 * 128];
__device__ float g_feat[128 * 128];
__device__ float g_md[128], g_fs[128], g_mf[128], g_mdist[128];
__device__ unsigned long long g_ckd[4][128], g_ckf[4][128];  // sharded col argmax
__device__ float g_W1T[512 * 256];          // W1 transposed: [input][channel]
__device__ unsigned long long g_h1i[256];   // fixed-point fc1 accumulators
__device__ unsigned g_ctr1, g_ctr2;

__device__ __forceinline__ unsigned f2o(float f) {
    unsigned u = __float_as_uint(f);
    return (u & 0x80000000u) ? ~u : (u | 0x80000000u);
}
// exact inverse of f2o
__device__ __forceinline__ float o2f(unsigned k) {
    return __uint_as_float((k & 0x80000000u) ? (k ^ 0x80000000u) : ~k);
}
__device__ __forceinline__ unsigned long long pk(float v, unsigned inv_idx) {
    return (((unsigned long long)f2o(v)) << 32) | (unsigned long long)inv_idx;
}
// release arrival / acquire spin (no L1 flush)
__device__ __forceinline__ void bar_arrive(unsigned* ctr) {
    asm volatile("red.release.gpu.add.u32 [%0], 1;" :: "l"(ctr) : "memory");
}
__device__ __forceinline__ void bar_spin(unsigned* ctr, unsigned target) {
    unsigned v;
    do {
        asm volatile("ld.acquire.gpu.u32 %0, [%1];" : "=r"(v) : "l"(ctr) : "memory");
    } while (v < target);
}

// butterfly multi-reduce: 8 independent sums across 32 lanes in 9 shuffles.
// On return lane group r = lane>>2 holds sum r in vv[0]; (lane&3)==0 writes.
__device__ __forceinline__ void butterfly8(float* vv, int lane) {
#pragma unroll
    for (int j = 0; j < 4; j++) {
        float give = (lane & 16) ? vv[j] : vv[j + 4];
        float got  = __shfl_xor_sync(0xffffffffu, give, 16);
        vv[j] = ((lane & 16) ? vv[j + 4] : vv[j]) + got;
    }
#pragma unroll
    for (int j = 0; j < 2; j++) {
        float give = (lane & 8) ? vv[j] : vv[j + 2];
        float got  = __shfl_xor_sync(0xffffffffu, give, 8);
        vv[j] = ((lane & 8) ? vv[j + 2] : vv[j]) + got;
    }
    {
        float give = (lane & 4) ? vv[0] : vv[1];
        float got  = __shfl_xor_sync(0xffffffffu, give, 4);
        vv[0] = ((lane & 4) ? vv[1] : vv[0]) + got;
    }
    vv[0] += __shfl_xor_sync(0xffffffffu, vv[0], 2);
    vv[0] += __shfl_xor_sync(0xffffffffu, vv[0], 1);
}

// 128-wide argmax scan from shared, one warp; returns packed key on all lanes
__device__ __forceinline__ unsigned long long scan128(const float* arr, int lane) {
    unsigned long long k = 0ull;
#pragma unroll
    for (int q = 0; q < 4; q++) {
        int idx = lane + 32 * q;
        unsigned long long c = pk(arr[idx], 127u - (unsigned)idx);
        if (c > k) k = c;
    }
#pragma unroll
    for (int o = 16; o > 0; o >>= 1) {
        unsigned long long oth = __shfl_xor_sync(0xffffffffu, k, o);
        if (oth > k) k = oth;
    }
    return k;
}

__global__ void __launch_bounds__(512)
k_all(const float* __restrict__ pts, const float* __restrict__ trans,
      const float* __restrict__ ref_f, const float* __restrict__ src_f,
      const float* __restrict__ W1, const float* __restrict__ b1,
      const float* __restrict__ gm1, const float* __restrict__ bt1,
      const float* __restrict__ W2, const float* __restrict__ b2,
      const float* __restrict__ gm2, const float* __restrict__ bt2,
      const float* __restrict__ W3, const float* __restrict__ b3,
      float* __restrict__ out) {
    __shared__ float spx[256], spy[256], spz[256];
    __shared__ float sdrowA[128], sdrowB[128], sfrowA[128], sfrowB[128];
    __shared__ float sred[24], smax[8];
    // block-0 tail params
    __shared__ float sg1[256], sb1g[256], sb1[256];
    __shared__ float sg2[128], sbt2[128], sb2[128], sb3[2];
    __shared__ __align__(16) float4 sW3[64];
    // post-barrier work
    __shared__ float smd[256], smf[256];
    __shared__ int   sidxd[128], sidxf[128];
    __shared__ __align__(16) unsigned long long sk1[256], sk2[256];
    __shared__ int   spos[8];
    __shared__ float sval[8];
    __shared__ __align__(16) float sha[256];
    __shared__ float sh2[128];
    __shared__ __align__(16) float sh2a[128];

    const int t = threadIdx.x;
    const int i = blockIdx.x;          // 64 blocks, 2 ref rows each
    const int w = t >> 5, lane = t & 31;
    const int slot = i & 3;
    const int ra = 2 * i, rb = 2 * i + 1;

    // ====== register prefetch: 2 ref rows + this warp's 8 src rows ======
    const float4* rfa = reinterpret_cast<const float4*>(ref_f) + (size_t)ra * 64;
    const float4* rfb = reinterpret_cast<const float4*>(ref_f) + (size_t)rb * 64;
    float4 r0a = __ldg(&rfa[lane]);
    float4 r1a = __ldg(&rfa[lane + 32]);
    float4 r0b = __ldg(&rfb[lane]);
    float4 r1b = __ldg(&rfb[lane + 32]);
    float4 a0[8], a1[8];
#pragma unroll
    for (int jj = 0; jj < 8; jj++) {
        const float4* s4 = reinterpret_cast<const float4*>(src_f + (size_t)(w * 8 + jj) * FD);
        a0[jj] = __ldg(&s4[lane]);
        a1[jj] = __ldg(&s4[lane + 32]);
    }
    // W1 transpose: this block owns input-columns p = 8i + (t>>6)
    const int p_in = 8 * i + (t >> 6);
    const int cq = (t & 63) * 4;       // 4 consecutive channels per thread
    float w1v0 = __ldg(&W1[(size_t)(cq + 0) * 512 + p_in]);
    float w1v1 = __ldg(&W1[(size_t)(cq + 1) * 512 + p_in]);
    float w1v2 = __ldg(&W1[(size_t)(cq + 2) * 512 + p_in]);
    float w1v3 = __ldg(&W1[(size_t)(cq + 3) * 512 + p_in]);

    // ============ block-0 tail param prefetch ============
    if (i == 0) {
        if (t < 256) {
            sg1[t]  = __ldg(&gm1[t]);
            sb1g[t] = __ldg(&bt1[t]);
            sb1[t]  = __ldg(&b1[t]);
        } else if (t < 384) {
            int q = t - 256;
            sg2[q]  = __ldg(&gm2[q]);
            sbt2[q] = __ldg(&bt2[q]);
            sb2[q]  = __ldg(&b2[q]);
        } else if (t < 448) {
            sW3[t - 384] = __ldg(&reinterpret_cast<const float4*>(W3)[t - 384]);
        } else if (t < 450) {
            sb3[t - 448] = __ldg(&b3[t - 448]);
        }
    }

    // ===================== Phase 1: normalize + my 2 rows ====================
    // Centroid cancels in pairwise diffs: d_ij = ||p_i - p_j||^2 / m^2.
    float tr0 = __ldg(&trans[0]), tr1 = __ldg(&trans[1]), tr2  = __ldg(&trans[2]),  tr3  = __ldg(&trans[3]);
    float tr4 = __ldg(&trans[4]), tr5 = __ldg(&trans[5]), tr6  = __ldg(&trans[6]),  tr7  = __ldg(&trans[7]);
    float tr8 = __ldg(&trans[8]), tr9 = __ldg(&trans[9]), tr10 = __ldg(&trans[10]), tr11 = __ldg(&trans[11]);

    float px = 0.f, py = 0.f, pz = 0.f;
    if (t < 256) {
        px = pts[3 * t + 0];
        py = pts[3 * t + 1];
        pz = pts[3 * t + 2];
        if (t >= 128) {
            float x = tr0 * px + tr1 * py + tr2  * pz + tr3;
            float y = tr4 * px + tr5 * py + tr6  * pz + tr7;
            float z = tr8 * px + tr9 * py + tr10 * pz + tr11;
            px = x; py = y; pz = z;
        }
        spx[t] = px; spy[t] = py; spz[t] = pz;
    }
    float lx = px, ly = py, lz = pz;
#pragma unroll
    for (int o = 16; o > 0; o >>= 1) {
        lx += __shfl_xor_sync(0xffffffffu, lx, o);
        ly += __shfl_xor_sync(0xffffffffu, ly, o);
        lz += __shfl_xor_sync(0xffffffffu, lz, o);
    }
    if (w < 8 && lane == 0) { sred[w] = lx; sred[8 + w] = ly; sred[16 + w] = lz; }
    __syncthreads();

    // raw pairwise sqdist for both rows (overlaps reductions)
    float rawdA = 0.f, rawdB = 0.f;
    if (t < 128) {
        float sx = spx[128 + t], sy = spy[128 + t], sz = spz[128 + t];
        float dxa = spx[ra] - sx, dya = spy[ra] - sy, dza = spz[ra] - sz;
        float dxb = spx[rb] - sx, dyb = spy[rb] - sy, dzb = spz[rb] - sz;
        rawdA = dxa * dxa + dya * dya + dza * dza;
        rawdB = dxb * dxb + dyb * dyb + dzb * dzb;
    }

    float cx = 0.f, cy = 0.f, cz = 0.f;
#pragma unroll
    for (int q = 0; q < 8; q++) { cx += sred[q]; cy += sred[8 + q]; cz += sred[16 + q]; }
    cx *= (1.0f / 256.0f); cy *= (1.0f / 256.0f); cz *= (1.0f / 256.0f);

    float sq = 0.f;
    if (t < 256) {
        float ex = px - cx, ey = py - cy, ez = pz - cz;
        sq = ex * ex + ey * ey + ez * ez;
    }
    float lm = sq;
#pragma unroll
    for (int o = 16; o > 0; o >>= 1)
        lm = fmaxf(lm, __shfl_xor_sync(0xffffffffu, lm, o));
    if (w < 8 && lane == 0) smax[w] = lm;
    __syncthreads();
    float m2 = smax[0];
#pragma unroll
    for (int q = 1; q < 8; q++) m2 = fmaxf(m2, smax[q]);
    float inv2 = 1.0f / m2;

    // dist entries for both rows
    if (t < 128) {
        float eA = expf(-(rawdA * inv2));
        float eB = expf(-(rawdB * inv2));
        g_dist[ra * 128 + t] = eA;
        g_dist[rb * 128 + t] = eB;
        sdrowA[t] = eA;
        sdrowB[t] = eB;
        unsigned long long kA = pk(eA, 127u - (unsigned)ra);
        unsigned long long kB = pk(eB, 127u - (unsigned)rb);
        atomicMax(&g_ckd[slot][t], (kA > kB) ? kA : kB);
    }

    // store transposed W1 columns (float4, coalesced within 64-thread groups)
    {
        float4 v = make_float4(w1v0, w1v1, w1v2, w1v3);
        *reinterpret_cast<float4*>(&g_W1T[p_in * 256 + cq]) = v;
    }

    // feat rows: 16 warps x 8 src rows x 2 ref rows, butterfly multi-reduce
    {
        float vv[8];
#pragma unroll
        for (int jj = 0; jj < 8; jj++) {
            vv[jj] = a0[jj].x * r0a.x + a0[jj].y * r0a.y + a0[jj].z * r0a.z + a0[jj].w * r0a.w
                   + a1[jj].x * r1a.x + a1[jj].y * r1a.y + a1[jj].z * r1a.z + a1[jj].w * r1a.w;
        }
        butterfly8(vv, lane);
        if ((lane & 3) == 0) sfrowA[w * 8 + (lane >> 2)] = vv[0];
#pragma unroll
        for (int jj = 0; jj < 8; jj++) {
            vv[jj] = a0[jj].x * r0b.x + a0[jj].y * r0b.y + a0[jj].z * r0b.z + a0[jj].w * r0b.w
                   + a1[jj].x * r1b.x + a1[jj].y * r1b.y + a1[jj].z * r1b.z + a1[jj].w * r1b.w;
        }
        butterfly8(vv, lane);
        if ((lane & 3) == 0) sfrowB[w * 8 + (lane >> 2)] = vv[0];
    }
    __syncthreads();
    if (t < 128) {
        float fA = sfrowA[t];
        float fB = sfrowB[t];
        g_feat[ra * 128 + t] = fA;
        g_feat[rb * 128 + t] = fB;
        unsigned long long kA = pk(fA, 127u - (unsigned)ra);
        unsigned long long kB = pk(fB, 127u - (unsigned)rb);
        atomicMax(&g_ckf[slot][t], (kA > kB) ? kA : kB);
    }
    // row argmaxes: 4 parallel warp scans
    if (w == 0) {
        unsigned long long k = scan128(sdrowA, lane);
        if (lane == 0) {
            int jd = 127 - (int)(k & 0xFFFFFFFFull);
            g_md[ra] = sdrowA[jd];
            g_fs[ra] = sfrowA[jd];
        }
    } else if (w == 1) {
        unsigned long long k = scan128(sfrowA, lane);
        if (lane == 0) {
            int jf = 127 - (int)(k & 0xFFFFFFFFull);
            g_mf[ra]    = sfrowA[jf];
            g_mdist[ra] = sdrowA[jf];
        }
    } else if (w == 2) {
        unsigned long long k = scan128(sdrowB, lane);
        if (lane == 0) {
            int jd = 127 - (int)(k & 0xFFFFFFFFull);
            g_md[rb] = sdrowB[jd];
            g_fs[rb] = sfrowB[jd];
        }
    } else if (w == 3) {
        unsigned long long k = scan128(sfrowB, lane);
        if (lane == 0) {
            int jf = 127 - (int)(k & 0xFFFFFFFFull);
            g_mf[rb]    = sfrowB[jf];
            g_mdist[rb] = sdrowB[jf];
        }
    }

    // ===================== grid barrier #1 =====================
    __syncthreads();
    if (t == 0) {
        bar_arrive(&g_ctr1);
        bar_spin(&g_ctr1, 64u);
    }
    __syncthreads();

    // ====== Phase 2: distributed assemble + rank own 8 + fused fc1 ==========
    // threads 0-127: row vectors; 256-383: dist-col decode; 384-511: feat-col
    if (t < 128) {
        float vmd = __ldcg(&g_md[t]);
        float vmf = __ldcg(&g_mf[t]);
        smd[t] = vmd;
        smf[t] = vmf;
        sk1[t] = pk(vmd, 255u - (unsigned)t);
        sk2[t] = pk(vmf, 255u - (unsigned)t);
    } else if (t >= 256 && t < 384) {
        int c = t - 256;
        unsigned long long kd = __ldcg(&g_ckd[0][c]);
#pragma unroll
        for (int s = 1; s < 4; s++) {
            unsigned long long ud = __ldcg(&g_ckd[s][c]);
            if (ud > kd) kd = ud;
        }
        float vmd = o2f((unsigned)(kd >> 32));   // col dist max (exact bits)
        smd[128 + c] = vmd;
        sidxd[c] = 127 - (int)(kd & 0xFFFFFFFFull);
        sk1[128 + c] = pk(vmd, 255u - (unsigned)(128 + c));
    } else if (t >= 384) {
        int c = t - 384;
        unsigned long long kf = __ldcg(&g_ckf[0][c]);
#pragma unroll
        for (int s = 1; s < 4; s++) {
            unsigned long long uf = __ldcg(&g_ckf[s][c]);
            if (uf > kf) kf = uf;
        }
        float vmf = o2f((unsigned)(kf >> 32));   // col feat max (exact bits)
        smf[128 + c] = vmf;
        sidxf[c] = 127 - (int)(kf & 0xFFFFFFFFull);
        sk2[128 + c] = pk(vmf, 255u - (unsigned)(128 + c));
    }

    // early index-free gathers for owned elements (overlap the assemble)
    float gval_early = 0.f;
    if (w < 8 && lane == 0) {
        int e = 8 * i + w;
        if (e < 128)                    gval_early = __ldcg(&g_fs[e]);
        else if (e >= 256 && e < 384)   gval_early = __ldcg(&g_mdist[e - 256]);
    }
    __syncthreads();

    // one warp per owned element (8 per block across 64 blocks = 512 total)
    if (w < 8) {
        int e = 8 * i + w;
        float gval = gval_early;
        if (lane == 0) {
            if (e >= 128 && e < 256)      { int c = e - 128; gval = __ldcg(&g_feat[sidxd[c] * 128 + c]); }
            else if (e >= 384)            { int c = e - 384; gval = __ldcg(&g_dist[sidxf[c] * 128 + c]); }
        }
        const unsigned long long* keys = (e < 256) ? sk1 : sk2;
        int c = (e < 256) ? e : (e - 256);
        unsigned long long mykey = keys[c];
        int cnt = 0;
#pragma unroll
        for (int jj = 0; jj < 8; jj++)
            cnt += (keys[jj * 32 + lane] > mykey) ? 1 : 0;
        cnt = __reduce_add_sync(0xffffffffu, cnt);
        if (lane == 0) {
            spos[w] = (e < 256) ? cnt : (256 + cnt);
            float keyval = (e < 256) ? smd[c] : smf[c];
            sval[w] = keyval * gval;
        }
    }
    __syncthreads();

    // fused fc1: this block's contribution to ALL 256 channels,
    // deterministic fixed-point accumulation
    if (t < 256) {
        float acc = 0.f;
#pragma unroll
        for (int q = 0; q < 8; q++)
            acc += __ldcg(&g_W1T[spos[q] * 256 + t]) * sval[q];
        long long qq = (long long)((double)acc * 4294967296.0);
        atomicAdd(&g_h1i[t], (unsigned long long)qq);
    }

    // block 0: issue W2 prefetch into registers BEFORE the barrier wait
    float4 wa0[8], wa1[8];
    if (i == 0) {
#pragma unroll
        for (int cc = 0; cc < 8; cc++) {
            int c = (w << 3) | cc;
            const float4* row = reinterpret_cast<const float4*>(W2 + (size_t)c * 256);
            wa0[cc] = __ldg(&row[lane]);
            wa1[cc] = __ldg(&row[lane + 32]);
        }
    }
    __syncthreads();

    // ===================== grid barrier #2 (h1 ready) =====================
    if (t == 0) bar_arrive(&g_ctr2);
    if (i != 0) return;                       // non-zero blocks done
    if (t == 0) bar_spin(&g_ctr2, 64u);
    __syncthreads();

    // ============== Tail (block 0): GN1+fc2+GN2+fc3 -> out ==================
    if (t < 256) {
        unsigned long long qv = __ldcg(&g_h1i[t]);
        float x = (float)((double)(long long)qv * (1.0 / 4294967296.0)) + sb1[t];
        g_h1i[t] = 0ull;   // reset for next replay (after consumption)
        float s = x;
#pragma unroll
        for (int o = 16; o > 0; o >>= 1) s += __shfl_xor_sync(0xffffffffu, s, o);
        float mean = s * (1.0f / 32.0f);
        float ee = x - mean;
        float v = ee * ee;
#pragma unroll
        for (int o = 16; o > 0; o >>= 1) v += __shfl_xor_sync(0xffffffffu, v, o);
        v *= (1.0f / 32.0f);
        float xn = ee / sqrtf(v + 1e-5f) * sg1[t] + sb1g[t];
        sha[t] = fmaxf(xn, 0.0f);
    }
    // reset colkeys (block 0 is the only survivor; all consumers are past)
    {
        int s = t >> 7, c = t & 127;
        g_ckd[s][c] = 0ull;
        g_ckf[s][c] = 0ull;
    }
    __syncthreads();

    // fc2: 16 warps x 8 channels, butterfly multi-reduce
    {
        const float4* ha4 = reinterpret_cast<const float4*>(sha);
        float4 h0 = ha4[lane], h1v = ha4[lane + 32];
        float vv[8];
#pragma unroll
        for (int cc = 0; cc < 8; cc++) {
            vv[cc] = wa0[cc].x * h0.x + wa0[cc].y * h0.y + wa0[cc].z * h0.z + wa0[cc].w * h0.w
                   + wa1[cc].x * h1v.x + wa1[cc].y * h1v.y + wa1[cc].z * h1v.z + wa1[cc].w * h1v.w;
        }
        butterfly8(vv, lane);
        if ((lane & 3) == 0) {
            int c = (w << 3) | (lane >> 2);
            sh2[c] = vv[0] + sb2[c];
        }
    }
    __syncthreads();

    // GN2 (8 groups x 16 = half-warp per group) + ReLU
    if (t < 128) {
        float x = sh2[t];
        float s = x;
#pragma unroll
        for (int o = 8; o > 0; o >>= 1) s += __shfl_xor_sync(0xffffffffu, s, o);
        float mean = s * (1.0f / 16.0f);
        float ee = x - mean;
        float v = ee * ee;
#pragma unroll
        for (int o = 8; o > 0; o >>= 1) v += __shfl_xor_sync(0xffffffffu, v, o);
        v *= (1.0f / 16.0f);
        float xn = ee / sqrtf(v + 1e-5f) * sg2[t] + sbt2[t];
        sh2a[t] = fmaxf(xn, 0.0f);
    }
    __syncthreads();

    // fc3: 128 -> 2
    if (w < 2) {
        float4 a = sW3[w * 32 + lane];
        float4 g = reinterpret_cast<const float4*>(sh2a)[lane];
        float acc = a.x * g.x + a.y * g.y + a.z * g.z + a.w * g.w;
#pragma unroll
        for (int o = 16; o > 0; o >>= 1)
            acc += __shfl_xor_sync(0xffffffffu, acc, o);
        if (lane == 0) out[w] = acc + sb3[w];
    }

    // reset barrier counters for next graph replay
    if (t == 0) { g_ctr1 = 0u; g_ctr2 = 0u; }
}

extern "C" void kernel_launch(void* const* d_in, const int* in_sizes, int n_in,
                              void* d_out, int out_size) {
    const float* pts   = (const float*)d_in[0];
    const float* reff  = (const float*)d_in[1];
    const float* srcf  = (const float*)d_in[2];
    const float* trans = (const float*)d_in[3];
    const float* W1  = (const float*)d_in[4];
    const float* b1  = (const float*)d_in[5];
    const float* g1  = (const float*)d_in[6];
    const float* bt1 = (const float*)d_in[7];
    const float* W2  = (const float*)d_in[8];
    const float* b2  = (const float*)d_in[9];
    const float* g2  = (const float*)d_in[10];
    const float* bt2 = (const float*)d_in[11];
    const float* W3  = (const float*)d_in[12];
    const float* b3  = (const float*)d_in[13];

    k_all<<<64, 512>>>(pts, trans, reff, srcf,
                       W1, b1, g1, bt1, W2, b2, g2, bt2, W3, b3,
                       (float*)d_out);
}

// round 16
// speedup vs baseline: 1.1328x; 1.1328x over previous
#include <cuda_runtime.h>
#include <math.h>

#define FD 256

// -------- device scratch (zero-initialized at module load) --------
__device__ float g_dist[128 * 128];
__device__ float g_feat[128 * 128];
__device__ float g_md[128], g_fs[128], g_mf[128], g_mdist[128];
__device__ unsigned long long g_ckd[4][128], g_ckf[4][128];  // sharded col argmax
__device__ float g_W1T[512 * 256];          // W1 transposed: [input][channel]
__device__ unsigned long long g_h1i[256];   // fixed-point fc1 accumulators
__device__ unsigned g_ctr1, g_ctr2;

__device__ __forceinline__ unsigned f2o(float f) {
    unsigned u = __float_as_uint(f);
    return (u & 0x80000000u) ? ~u : (u | 0x80000000u);
}
// exact inverse of f2o
__device__ __forceinline__ float o2f(unsigned k) {
    return __uint_as_float((k & 0x80000000u) ? (k ^ 0x80000000u) : ~k);
}
__device__ __forceinline__ unsigned long long pk(float v, unsigned inv_idx) {
    return (((unsigned long long)f2o(v)) << 32) | (unsigned long long)inv_idx;
}
// release arrival / acquire spin (no L1 flush)
__device__ __forceinline__ void bar_arrive(unsigned* ctr) {
    asm volatile("red.release.gpu.add.u32 [%0], 1;" :: "l"(ctr) : "memory");
}
__device__ __forceinline__ void bar_spin(unsigned* ctr, unsigned target) {
    unsigned v;
    do {
        asm volatile("ld.acquire.gpu.u32 %0, [%1];" : "=r"(v) : "l"(ctr) : "memory");
    } while (v < target);
}

// butterfly multi-reduce: 8 independent sums across 32 lanes in 9 shuffles.
// On return lane group r = lane>>2 holds sum r in vv[0]; (lane&3)==0 writes.
__device__ __forceinline__ void butterfly8(float* vv, int lane) {
#pragma unroll
    for (int j = 0; j < 4; j++) {
        float give = (lane & 16) ? vv[j] : vv[j + 4];
        float got  = __shfl_xor_sync(0xffffffffu, give, 16);
        vv[j] = ((lane & 16) ? vv[j + 4] : vv[j]) + got;
    }
#pragma unroll
    for (int j = 0; j < 2; j++) {
        float give = (lane & 8) ? vv[j] : vv[j + 2];
        float got  = __shfl_xor_sync(0xffffffffu, give, 8);
        vv[j] = ((lane & 8) ? vv[j + 2] : vv[j]) + got;
    }
    {
        float give = (lane & 4) ? vv[0] : vv[1];
        float got  = __shfl_xor_sync(0xffffffffu, give, 4);
        vv[0] = ((lane & 4) ? vv[1] : vv[0]) + got;
    }
    vv[0] += __shfl_xor_sync(0xffffffffu, vv[0], 2);
    vv[0] += __shfl_xor_sync(0xffffffffu, vv[0], 1);
}

// 128-wide argmax scan from shared, one warp; returns packed key on lane 0
__device__ __forceinline__ unsigned long long scan128(const float* arr, int lane) {
    unsigned long long k = 0ull;
#pragma unroll
    for (int q = 0; q < 4; q++) {
        int idx = lane + 32 * q;
        unsigned long long c = pk(arr[idx], 127u - (unsigned)idx);
        if (c > k) k = c;
    }
#pragma unroll
    for (int o = 16; o > 0; o >>= 1) {
        unsigned long long oth = __shfl_xor_sync(0xffffffffu, k, o);
        if (oth > k) k = oth;
    }
    return k;
}

__global__ void __launch_bounds__(512)
k_all(const float* __restrict__ pts, const float* __restrict__ trans,
      const float* __restrict__ ref_f, const float* __restrict__ src_f,
      const float* __restrict__ W1, const float* __restrict__ b1,
      const float* __restrict__ gm1, const float* __restrict__ bt1,
      const float* __restrict__ W2, const float* __restrict__ b2,
      const float* __restrict__ gm2, const float* __restrict__ bt2,
      const float* __restrict__ W3, const float* __restrict__ b3,
      float* __restrict__ out) {
    __shared__ float spx[256], spy[256], spz[256];
    __shared__ float sdrowA[128], sdrowB[128], sfrowA[128], sfrowB[128];
    __shared__ float sred[24], smax[8];
    // block-0 tail params
    __shared__ float sg1[256], sb1g[256], sb1[256];
    __shared__ float sg2[128], sbt2[128], sb2[128], sb3[2];
    __shared__ __align__(16) float4 sW3[64];
    // post-barrier work
    __shared__ float smd[256], smf[256];
    __shared__ int   sidxd[128], sidxf[128];
    __shared__ __align__(16) unsigned long long sk1[256], sk2[256];
    __shared__ int   spos[8];
    __shared__ float sval[8];
    __shared__ __align__(16) float sha[256];
    __shared__ float sh2[128];
    __shared__ __align__(16) float sh2a[128];

    const int t = threadIdx.x;
    const int i = blockIdx.x;          // 64 blocks, 2 ref rows each
    const int w = t >> 5, lane = t & 31;
    const int slot = i & 3;
    const int ra = 2 * i, rb = 2 * i + 1;

    // ====== register prefetch: 2 ref rows + this warp's 8 src rows ======
    const float4* rfa = reinterpret_cast<const float4*>(ref_f) + (size_t)ra * 64;
    const float4* rfb = reinterpret_cast<const float4*>(ref_f) + (size_t)rb * 64;
    float4 r0a = __ldg(&rfa[lane]);
    float4 r1a = __ldg(&rfa[lane + 32]);
    float4 r0b = __ldg(&rfb[lane]);
    float4 r1b = __ldg(&rfb[lane + 32]);
    float4 a0[8], a1[8];
#pragma unroll
    for (int jj = 0; jj < 8; jj++) {
        const float4* s4 = reinterpret_cast<const float4*>(src_f + (size_t)(w * 8 + jj) * FD);
        a0[jj] = __ldg(&s4[lane]);
        a1[jj] = __ldg(&s4[lane + 32]);
    }
    // W1 transpose: this block owns input-columns p = 8i + (t>>6)
    const int p_in = 8 * i + (t >> 6);
    const int cq = (t & 63) * 4;       // 4 consecutive channels per thread
    float w1v0 = __ldg(&W1[(size_t)(cq + 0) * 512 + p_in]);
    float w1v1 = __ldg(&W1[(size_t)(cq + 1) * 512 + p_in]);
    float w1v2 = __ldg(&W1[(size_t)(cq + 2) * 512 + p_in]);
    float w1v3 = __ldg(&W1[(size_t)(cq + 3) * 512 + p_in]);

    // ============ block-0 tail param prefetch ============
    if (i == 0) {
        if (t < 256) {
            sg1[t]  = __ldg(&gm1[t]);
            sb1g[t] = __ldg(&bt1[t]);
            sb1[t]  = __ldg(&b1[t]);
        } else if (t < 384) {
            int q = t - 256;
            sg2[q]  = __ldg(&gm2[q]);
            sbt2[q] = __ldg(&bt2[q]);
            sb2[q]  = __ldg(&b2[q]);
        } else if (t < 448) {
            sW3[t - 384] = __ldg(&reinterpret_cast<const float4*>(W3)[t - 384]);
        } else if (t < 450) {
            sb3[t - 448] = __ldg(&b3[t - 448]);
        }
    }

    // ===================== Phase 1: normalize + my 2 rows ====================
    // Centroid cancels in pairwise diffs: d_ij = ||p_i - p_j||^2 / m^2.
    float tr0 = __ldg(&trans[0]), tr1 = __ldg(&trans[1]), tr2  = __ldg(&trans[2]),  tr3  = __ldg(&trans[3]);
    float tr4 = __ldg(&trans[4]), tr5 = __ldg(&trans[5]), tr6  = __ldg(&trans[6]),  tr7  = __ldg(&trans[7]);
    float tr8 = __ldg(&trans[8]), tr9 = __ldg(&trans[9]), tr10 = __ldg(&trans[10]), tr11 = __ldg(&trans[11]);

    float px = 0.f, py = 0.f, pz = 0.f;
    if (t < 256) {
        px = pts[3 * t + 0];
        py = pts[3 * t + 1];
        pz = pts[3 * t + 2];
        if (t >= 128) {
            float x = tr0 * px + tr1 * py + tr2  * pz + tr3;
            float y = tr4 * px + tr5 * py + tr6  * pz + tr7;
            float z = tr8 * px + tr9 * py + tr10 * pz + tr11;
            px = x; py = y; pz = z;
        }
        spx[t] = px; spy[t] = py; spz[t] = pz;
    }
    float lx = px, ly = py, lz = pz;
#pragma unroll
    for (int o = 16; o > 0; o >>= 1) {
        lx += __shfl_xor_sync(0xffffffffu, lx, o);
        ly += __shfl_xor_sync(0xffffffffu, ly, o);
        lz += __shfl_xor_sync(0xffffffffu, lz, o);
    }
    if (w < 8 && lane == 0) { sred[w] = lx; sred[8 + w] = ly; sred[16 + w] = lz; }
    __syncthreads();

    // raw pairwise sqdist for both rows (overlaps reductions)
    float rawdA = 0.f, rawdB = 0.f;
    if (t < 128) {
        float sx = spx[128 + t], sy = spy[128 + t], sz = spz[128 + t];
        float dxa = spx[ra] - sx, dya = spy[ra] - sy, dza = spz[ra] - sz;
        float dxb = spx[rb] - sx, dyb = spy[rb] - sy, dzb = spz[rb] - sz;
        rawdA = dxa * dxa + dya * dya + dza * dza;
        rawdB = dxb * dxb + dyb * dyb + dzb * dzb;
    }

    float cx = 0.f, cy = 0.f, cz = 0.f;
#pragma unroll
    for (int q = 0; q < 8; q++) { cx += sred[q]; cy += sred[8 + q]; cz += sred[16 + q]; }
    cx *= (1.0f / 256.0f); cy *= (1.0f / 256.0f); cz *= (1.0f / 256.0f);

    float sq = 0.f;
    if (t < 256) {
        float ex = px - cx, ey = py - cy, ez = pz - cz;
        sq = ex * ex + ey * ey + ez * ez;
    }
    float lm = sq;
#pragma unroll
    for (int o = 16; o > 0; o >>= 1)
        lm = fmaxf(lm, __shfl_xor_sync(0xffffffffu, lm, o));
    if (w < 8 && lane == 0) smax[w] = lm;
    __syncthreads();
    float m2 = smax[0];
#pragma unroll
    for (int q = 1; q < 8; q++) m2 = fmaxf(m2, smax[q]);
    float inv2 = 1.0f / m2;

    // dist entries for both rows
    if (t < 128) {
        float eA = expf(-(rawdA * inv2));
        float eB = expf(-(rawdB * inv2));
        g_dist[ra * 128 + t] = eA;
        g_dist[rb * 128 + t] = eB;
        sdrowA[t] = eA;
        sdrowB[t] = eB;
        unsigned long long kA = pk(eA, 127u - (unsigned)ra);
        unsigned long long kB = pk(eB, 127u - (unsigned)rb);
        atomicMax(&g_ckd[slot][t], (kA > kB) ? kA : kB);
    }

    // store transposed W1 columns (float4, coalesced within 64-thread groups)
    {
        float4 v = make_float4(w1v0, w1v1, w1v2, w1v3);
        *reinterpret_cast<float4*>(&g_W1T[p_in * 256 + cq]) = v;
    }

    // feat rows: 16 warps x 8 src rows x 2 ref rows, butterfly multi-reduce
    {
        float vv[8];
#pragma unroll
        for (int jj = 0; jj < 8; jj++) {
            vv[jj] = a0[jj].x * r0a.x + a0[jj].y * r0a.y + a0[jj].z * r0a.z + a0[jj].w * r0a.w
                   + a1[jj].x * r1a.x + a1[jj].y * r1a.y + a1[jj].z * r1a.z + a1[jj].w * r1a.w;
        }
        butterfly8(vv, lane);
        if ((lane & 3) == 0) sfrowA[w * 8 + (lane >> 2)] = vv[0];
#pragma unroll
        for (int jj = 0; jj < 8; jj++) {
            vv[jj] = a0[jj].x * r0b.x + a0[jj].y * r0b.y + a0[jj].z * r0b.z + a0[jj].w * r0b.w
                   + a1[jj].x * r1b.x + a1[jj].y * r1b.y + a1[jj].z * r1b.z + a1[jj].w * r1b.w;
        }
        butterfly8(vv, lane);
        if ((lane & 3) == 0) sfrowB[w * 8 + (lane >> 2)] = vv[0];
    }
    __syncthreads();
    if (t < 128) {
        float fA = sfrowA[t];
        float fB = sfrowB[t];
        g_feat[ra * 128 + t] = fA;
        g_feat[rb * 128 + t] = fB;
        unsigned long long kA = pk(fA, 127u - (unsigned)ra);
        unsigned long long kB = pk(fB, 127u - (unsigned)rb);
        atomicMax(&g_ckf[slot][t], (kA > kB) ? kA : kB);
    }
    // row argmaxes: 4 parallel warp scans
    if (w == 0) {
        unsigned long long k = scan128(sdrowA, lane);
        if (lane == 0) {
            int jd = 127 - (int)(k & 0xFFFFFFFFull);
            g_md[ra] = sdrowA[jd];
            g_fs[ra] = sfrowA[jd];
        }
    } else if (w == 1) {
        unsigned long long k = scan128(sfrowA, lane);
        if (lane == 0) {
            int jf = 127 - (int)(k & 0xFFFFFFFFull);
            g_mf[ra]    = sfrowA[jf];
            g_mdist[ra] = sdrowA[jf];
        }
    } else if (w == 2) {
        unsigned long long k = scan128(sdrowB, lane);
        if (lane == 0) {
            int jd = 127 - (int)(k & 0xFFFFFFFFull);
            g_md[rb] = sdrowB[jd];
            g_fs[rb] = sfrowB[jd];
        }
    } else if (w == 3) {
        unsigned long long k = scan128(sfrowB, lane);
        if (lane == 0) {
            int jf = 127 - (int)(k & 0xFFFFFFFFull);
            g_mf[rb]    = sfrowB[jf];
            g_mdist[rb] = sdrowB[jf];
        }
    }

    // ===================== grid barrier #1 =====================
    __syncthreads();
    if (t == 0) {
        bar_arrive(&g_ctr1);
        bar_spin(&g_ctr1, 64u);
    }
    __syncthreads();

    // ====== Phase 2: slim assemble (keys only) + rank own 8 + fused fc1 =====
    if (t < 128) {
        float vmd = __ldcg(&g_md[t]);
        float vmf = __ldcg(&g_mf[t]);
        smd[t] = vmd;
        smf[t] = vmf;
        sk1[t] = pk(vmd, 255u - (unsigned)t);
        sk2[t] = pk(vmf, 255u - (unsigned)t);
    } else if (t < 256) {
        int c = t - 128;
        unsigned long long kd = __ldcg(&g_ckd[0][c]);
        unsigned long long kf = __ldcg(&g_ckf[0][c]);
#pragma unroll
        for (int s = 1; s < 4; s++) {
            unsigned long long ud = __ldcg(&g_ckd[s][c]);
            unsigned long long uf = __ldcg(&g_ckf[s][c]);
            if (ud > kd) kd = ud;
            if (uf > kf) kf = uf;
        }
        float vmd = o2f((unsigned)(kd >> 32));   // col dist max (exact bits)
        float vmf = o2f((unsigned)(kf >> 32));   // col feat max (exact bits)
        smd[t] = vmd;
        smf[t] = vmf;
        sidxd[c] = 127 - (int)(kd & 0xFFFFFFFFull);
        sidxf[c] = 127 - (int)(kf & 0xFFFFFFFFull);
        sk1[t] = pk(vmd, 255u - (unsigned)t);
        sk2[t] = pk(vmf, 255u - (unsigned)t);
    }
    __syncthreads();

    // one warp per owned element (8 per block across 64 blocks = 512 total)
    if (w < 8) {
        int e = 8 * i + w;
        // issue the single value-gather early (lane 0 only)
        float gval = 0.f;
        if (lane == 0) {
            if (e < 128)       gval = __ldcg(&g_fs[e]);
            else if (e < 256)  { int c = e - 128; gval = __ldcg(&g_feat[sidxd[c] * 128 + c]); }
            else if (e < 384)  gval = __ldcg(&g_mdist[e - 256]);
            else               { int c = e - 384; gval = __ldcg(&g_dist[sidxf[c] * 128 + c]); }
        }
        const unsigned long long* keys = (e < 256) ? sk1 : sk2;
        int c = (e < 256) ? e : (e - 256);
        unsigned long long mykey = keys[c];
        int cnt = 0;
#pragma unroll
        for (int jj = 0; jj < 8; jj++)
            cnt += (keys[jj * 32 + lane] > mykey) ? 1 : 0;
        cnt = __reduce_add_sync(0xffffffffu, cnt);
        if (lane == 0) {
            spos[w] = (e < 256) ? cnt : (256 + cnt);
            float keyval = (e < 256) ? smd[c] : smf[c];
            sval[w] = keyval * gval;
        }
    }
    __syncthreads();

    // fused fc1: this block's contribution to ALL 256 channels,
    // deterministic fixed-point accumulation
    if (t < 256) {
        float acc = 0.f;
#pragma unroll
        for (int q = 0; q < 8; q++)
            acc += __ldcg(&g_W1T[spos[q] * 256 + t]) * sval[q];
        long long qq = (long long)((double)acc * 4294967296.0);
        atomicAdd(&g_h1i[t], (unsigned long long)qq);
    }

    // block 0: issue W2 prefetch into registers BEFORE the barrier wait
    float4 wa0[8], wa1[8];
    if (i == 0) {
#pragma unroll
        for (int cc = 0; cc < 8; cc++) {
            int c = (w << 3) | cc;
            const float4* row = reinterpret_cast<const float4*>(W2 + (size_t)c * 256);
            wa0[cc] = __ldg(&row[lane]);
            wa1[cc] = __ldg(&row[lane + 32]);
        }
    }
    __syncthreads();

    // ===================== grid barrier #2 (h1 ready) =====================
    if (t == 0) bar_arrive(&g_ctr2);
    if (i != 0) return;                       // non-zero blocks done
    if (t == 0) bar_spin(&g_ctr2, 64u);
    __syncthreads();

    // ============== Tail (block 0): GN1+fc2+GN2+fc3 -> out ==================
    if (t < 256) {
        unsigned long long qv = __ldcg(&g_h1i[t]);
        float x = (float)((double)(long long)qv * (1.0 / 4294967296.0)) + sb1[t];
        g_h1i[t] = 0ull;   // reset for next replay (after consumption)
        float s = x;
#pragma unroll
        for (int o = 16; o > 0; o >>= 1) s += __shfl_xor_sync(0xffffffffu, s, o);
        float mean = s * (1.0f / 32.0f);
        float ee = x - mean;
        float v = ee * ee;
#pragma unroll
        for (int o = 16; o > 0; o >>= 1) v += __shfl_xor_sync(0xffffffffu, v, o);
        v *= (1.0f / 32.0f);
        float xn = ee / sqrtf(v + 1e-5f) * sg1[t] + sb1g[t];
        sha[t] = fmaxf(xn, 0.0f);
    }
    // reset colkeys (block 0 is the only survivor; all consumers are past)
    {
        int s = t >> 7, c = t & 127;
        g_ckd[s][c] = 0ull;
        g_ckf[s][c] = 0ull;
    }
    __syncthreads();

    // fc2: 16 warps x 8 channels, butterfly multi-reduce
    {
        const float4* ha4 = reinterpret_cast<const float4*>(sha);
        float4 h0 = ha4[lane], h1v = ha4[lane + 32];
        float vv[8];
#pragma unroll
        for (int cc = 0; cc < 8; cc++) {
            vv[cc] = wa0[cc].x * h0.x + wa0[cc].y * h0.y + wa0[cc].z * h0.z + wa0[cc].w * h0.w
                   + wa1[cc].x * h1v.x + wa1[cc].y * h1v.y + wa1[cc].z * h1v.z + wa1[cc].w * h1v.w;
        }
        butterfly8(vv, lane);
        if ((lane & 3) == 0) {
            int c = (w << 3) | (lane >> 2);
            sh2[c] = vv[0] + sb2[c];
        }
    }
    __syncthreads();

    // GN2 (8 groups x 16 = half-warp per group) + ReLU
    if (t < 128) {
        float x = sh2[t];
        float s = x;
#pragma unroll
        for (int o = 8; o > 0; o >>= 1) s += __shfl_xor_sync(0xffffffffu, s, o);
        float mean = s * (1.0f / 16.0f);
        float ee = x - mean;
        float v = ee * ee;
#pragma unroll
        for (int o = 8; o > 0; o >>= 1) v += __shfl_xor_sync(0xffffffffu, v, o);
        v *= (1.0f / 16.0f);
        float xn = ee / sqrtf(v + 1e-5f) * sg2[t] + sbt2[t];
        sh2a[t] = fmaxf(xn, 0.0f);
    }
    __syncthreads();

    // fc3: 128 -> 2
    if (w < 2) {
        float4 a = sW3[w * 32 + lane];
        float4 g = reinterpret_cast<const float4*>(sh2a)[lane];
        float acc = a.x * g.x + a.y * g.y + a.z * g.z + a.w * g.w;
#pragma unroll
        for (int o = 16; o > 0; o >>= 1)
            acc += __shfl_xor_sync(0xffffffffu, acc, o);
        if (lane == 0) out[w] = acc + sb3[w];
    }

    // reset barrier counters for next graph replay
    if (t == 0) { g_ctr1 = 0u; g_ctr2 = 0u; }
}

extern "C" void kernel_launch(void* const* d_in, const int* in_sizes, int n_in,
                              void* d_out, int out_size) {
    const float* pts   = (const float*)d_in[0];
    const float* reff  = (const float*)d_in[1];
    const float* srcf  = (const float*)d_in[2];
    const float* trans = (const float*)d_in[3];
    const float* W1  = (const float*)d_in[4];
    const float* b1  = (const float*)d_in[5];
    const float* g1  = (const float*)d_in[6];
    const float* bt1 = (const float*)d_in[7];
    const float* W2  = (const float*)d_in[8];
    const float* b2  = (const float*)d_in[9];
    const float* g2  = (const float*)d_in[10];
    const float* bt2 = (const float*)d_in[11];
    const float* W3  = (const float*)d_in[12];
    const float* b3  = (const float*)d_in[13];

    k_all<<<64, 512>>>(pts, trans, reff, srcf,
                       W1, b1, g1, bt1, W2, b2, g2, bt2, W3, b3,
                       (float*)d_out);
}